// round 15
// baseline (speedup 1.0000x reference)
#include <cuda_runtime.h>
#include <cstdint>

#define SS    80
#define HID   512
#define NPIX  8192      // 8 images * 32*32
#define KCONV 720       // 80 * 9
#define CA_THRESH 0.01f

// Internal buffers (allocation-free: __device__ globals)
__device__ float g_state[SS * NPIX];
__device__ float g_tmp[SS * NPIX];
__device__ float g_perc[HID * NPIX];
__device__ float g_h[HID * NPIX];
__device__ unsigned char g_pre[NPIX];

// ---------------------------------------------------------------------------
// helpers
// ---------------------------------------------------------------------------
__device__ __forceinline__ float tf32r(float x) {
    uint32_t u; asm("cvt.rna.tf32.f32 %0, %1;" : "=r"(u) : "f"(x));
    return __uint_as_float(u);
}

#define MMA_TF32(c, a0_, a1_, a2_, a3_, b0_, b1_) \
    asm volatile("mma.sync.aligned.m16n8k8.row.col.f32.tf32.tf32.f32 " \
        "{%0,%1,%2,%3}, {%4,%5,%6,%7}, {%8,%9}, {%0,%1,%2,%3};" \
        : "+f"((c)[0]), "+f"((c)[1]), "+f"((c)[2]), "+f"((c)[3]) \
        : "r"(a0_), "r"(a1_), "r"(a2_), "r"(a3_), "r"(b0_), "r"(b1_))

// smem row stride for [k][x] tiles: 136 floats (136 mod 32 = 8 -> fragment
// reads at banks 8*lc+lr, all 32 distinct; conflict-free).
#define RS 136

// ---------------------------------------------------------------------------
// init
// ---------------------------------------------------------------------------
__global__ void k_zero_state() {
    int i = blockIdx.x * blockDim.x + threadIdx.x;
    if (i < SS * NPIX) g_state[i] = 0.f;
}

__global__ void k_init(const float* __restrict__ z) {
    int t = blockIdx.x * blockDim.x + threadIdx.x;
    if (t >= 8 * SS) return;
    int n = t / SS, c = t % SS;
    int p = n * 1024 + 16 * 32 + 16;
    float v = (c == 0) ? 1.0f : z[n * 100 + (c - 1)];
    g_state[c * NPIX + p] = v;
}

__device__ __forceinline__ float maxpool3(const float* __restrict__ row, int p) {
    int x = p & 31, y = (p >> 5) & 31;
    float m = -1e30f;
    #pragma unroll
    for (int dy = -1; dy <= 1; dy++) {
        int yy = y + dy;
        if ((unsigned)yy >= 32u) continue;
        #pragma unroll
        for (int dx = -1; dx <= 1; dx++) {
            int xx = x + dx;
            if ((unsigned)xx >= 32u) continue;
            m = fmaxf(m, row[p + dy * 32 + dx]);
        }
    }
    return m;
}

__global__ void k_pre() {
    int p = blockIdx.x * blockDim.x + threadIdx.x;
    if (p >= NPIX) return;
    g_pre[p] = (maxpool3(g_state, p) > CA_THRESH) ? 1 : 0;
}

// ---------------------------------------------------------------------------
// GEMM1 (mma tf32x3): perception = W1 (*) im2col(state) + b1  (512x8192x720)
// CTA 128m x 128n, 256 thr (8 warps: wm=wid&3 m-split, wn=wid>>2 n-split).
// smem tiles As_h/As_l [16][RS] (k-major, m columns), Bs_h/Bs_l [16][RS].
// Single-buffered; register prefetch of next chunk overlaps compute.
// ---------------------------------------------------------------------------
__global__ __launch_bounds__(256) void k_gemm_conv(const float* __restrict__ W1,
                                                   const float* __restrict__ b1,
                                                   int s) {
    const int bm = blockIdx.y * 128;
    const int bn = blockIdx.x * 128;

    // active-box early exit (output rows [14-s, 18+s]); block-uniform
    const int y0 = (bn & 1023) >> 5;
    if (y0 + 3 < 14 - s || y0 > 18 + s) return;

    __shared__ float sAh[16 * RS], sAl[16 * RS];
    __shared__ float sBh[16 * RS], sBl[16 * RS];

    const int tid  = threadIdx.x;
    const int wid  = tid >> 5, lane = tid & 31;
    const int wm   = wid & 3,  wn   = wid >> 2;
    const int lr   = lane >> 2, lc  = lane & 3;

    // A-stage identity: f4 = tid + it*256 -> m = f4>>2, kq = (f4&3)*4
    const int am  = tid >> 2;
    const int akq = (tid & 3) * 4;
    // B-gather identity
    const int nb = tid & 127;
    const int p  = bn + nb;
    const int x  = p & 31, y = (p >> 5) & 31;
    const int kb = tid >> 7;   // 0 or 1

    float acc[2][8][4];
    #pragma unroll
    for (int mi = 0; mi < 2; mi++)
        #pragma unroll
        for (int ni = 0; ni < 8; ni++)
            #pragma unroll
            for (int cr = 0; cr < 4; cr++) acc[mi][ni][cr] = 0.f;

    float4 pa[2];
    float  pb[8];

    auto ldA = [&](int k0) {
        pa[0] = *reinterpret_cast<const float4*>(&W1[(bm + am)      * KCONV + k0 + akq]);
        pa[1] = *reinterpret_cast<const float4*>(&W1[(bm + am + 64) * KCONV + k0 + akq]);
    };
    auto ldB = [&](int k0) {
        #pragma unroll
        for (int it = 0; it < 8; it++) {
            int k  = k0 + kb + it * 2;
            int ci = k / 9;
            int r  = k - ci * 9;
            int dy = r / 3 - 1;
            int dx = r - (dy + 1) * 3 - 1;
            int yy = y + dy, xx = x + dx;
            float v = 0.f;
            if ((unsigned)yy < 32u && (unsigned)xx < 32u)
                v = g_state[ci * NPIX + p + dy * 32 + dx];
            pb[it] = v;
        }
    };
    auto stAB = [&]() {
        #pragma unroll
        for (int it = 0; it < 2; it++) {
            const int m = am + it * 64;
            const float vv[4] = {pa[it].x, pa[it].y, pa[it].z, pa[it].w};
            #pragma unroll
            for (int j = 0; j < 4; j++) {
                float hi = tf32r(vv[j]);
                sAh[(akq + j) * RS + m] = hi;
                sAl[(akq + j) * RS + m] = tf32r(vv[j] - hi);
            }
        }
        #pragma unroll
        for (int it = 0; it < 8; it++) {
            float hi = tf32r(pb[it]);
            sBh[(kb + it * 2) * RS + nb] = hi;
            sBl[(kb + it * 2) * RS + nb] = tf32r(pb[it] - hi);
        }
    };

    ldA(0); ldB(0);
    stAB();
    __syncthreads();

    const int NCH = KCONV / 16;   // 45
    #pragma unroll 1
    for (int c = 0; c < NCH; c++) {
        const bool more = (c + 1 < NCH);
        if (more) { ldA((c + 1) * 16); ldB((c + 1) * 16); }

        #pragma unroll
        for (int k8 = 0; k8 < 16; k8 += 8) {
            const int krow = (k8 + lc) * RS;
            uint32_t ah[2][4], al[2][4];
            #pragma unroll
            for (int mi = 0; mi < 2; mi++) {
                const int mb = wm * 32 + mi * 16 + lr;
                ah[mi][0] = __float_as_uint(sAh[krow + mb]);
                ah[mi][1] = __float_as_uint(sAh[krow + mb + 8]);
                ah[mi][2] = __float_as_uint(sAh[krow + 4 * RS + mb]);
                ah[mi][3] = __float_as_uint(sAh[krow + 4 * RS + mb + 8]);
                al[mi][0] = __float_as_uint(sAl[krow + mb]);
                al[mi][1] = __float_as_uint(sAl[krow + mb + 8]);
                al[mi][2] = __float_as_uint(sAl[krow + 4 * RS + mb]);
                al[mi][3] = __float_as_uint(sAl[krow + 4 * RS + mb + 8]);
            }
            #pragma unroll
            for (int ni = 0; ni < 8; ni++) {
                const int nbase = wn * 64 + ni * 8 + lr;
                const uint32_t bh0 = __float_as_uint(sBh[krow + nbase]);
                const uint32_t bh1 = __float_as_uint(sBh[krow + 4 * RS + nbase]);
                const uint32_t bl0 = __float_as_uint(sBl[krow + nbase]);
                const uint32_t bl1 = __float_as_uint(sBl[krow + 4 * RS + nbase]);
                #pragma unroll
                for (int mi = 0; mi < 2; mi++) {
                    MMA_TF32(acc[mi][ni], ah[mi][0], ah[mi][1], ah[mi][2], ah[mi][3], bh0, bh1);
                    MMA_TF32(acc[mi][ni], ah[mi][0], ah[mi][1], ah[mi][2], ah[mi][3], bl0, bl1);
                    MMA_TF32(acc[mi][ni], al[mi][0], al[mi][1], al[mi][2], al[mi][3], bh0, bh1);
                }
            }
        }

        __syncthreads();
        if (more) { stAB(); __syncthreads(); }
    }

    // epilogue: +bias
    float bv[2][2];
    #pragma unroll
    for (int mi = 0; mi < 2; mi++)
        #pragma unroll
        for (int hh = 0; hh < 2; hh++)
            bv[mi][hh] = b1[bm + wm * 32 + mi * 16 + lr + hh * 8];

    #pragma unroll
    for (int mi = 0; mi < 2; mi++)
        #pragma unroll
        for (int ni = 0; ni < 8; ni++)
            #pragma unroll
            for (int cr = 0; cr < 4; cr++) {
                const int m   = bm + wm * 32 + mi * 16 + lr + (cr >> 1) * 8;
                const int pix = bn + wn * 64 + ni * 8 + lc * 2 + (cr & 1);
                g_perc[m * NPIX + pix] = acc[mi][ni][cr] + bv[mi][cr >> 1];
            }
}

// ---------------------------------------------------------------------------
// GEMM2 (mma tf32x3): h = relu(W2 @ perception + b2)   (512 x 8192 x 512)
// ---------------------------------------------------------------------------
__global__ __launch_bounds__(256) void k_gemm_h(const float* __restrict__ W2,
                                                const float* __restrict__ b2,
                                                int s) {
    const int bm = blockIdx.y * 128;
    const int bn = blockIdx.x * 128;

    const int y0 = (bn & 1023) >> 5;
    if (y0 + 3 < 14 - s || y0 > 18 + s) return;

    __shared__ float sAh[16 * RS], sAl[16 * RS];
    __shared__ float sBh[16 * RS], sBl[16 * RS];

    const int tid  = threadIdx.x;
    const int wid  = tid >> 5, lane = tid & 31;
    const int wm   = wid & 3,  wn   = wid >> 2;
    const int lr   = lane >> 2, lc  = lane & 3;

    const int am  = tid >> 2;
    const int akq = (tid & 3) * 4;
    // B-stage identity: f4 = tid + it*256 -> k = f4>>5, nq = (f4&31)*4
    const int bk  = tid >> 5;
    const int bnq = (tid & 31) * 4;

    float acc[2][8][4];
    #pragma unroll
    for (int mi = 0; mi < 2; mi++)
        #pragma unroll
        for (int ni = 0; ni < 8; ni++)
            #pragma unroll
            for (int cr = 0; cr < 4; cr++) acc[mi][ni][cr] = 0.f;

    float4 pa[2], pb[2];

    auto ldA = [&](int k0) {
        pa[0] = *reinterpret_cast<const float4*>(&W2[(bm + am)      * HID + k0 + akq]);
        pa[1] = *reinterpret_cast<const float4*>(&W2[(bm + am + 64) * HID + k0 + akq]);
    };
    auto ldB = [&](int k0) {
        pb[0] = *reinterpret_cast<const float4*>(&g_perc[(k0 + bk)     * NPIX + bn + bnq]);
        pb[1] = *reinterpret_cast<const float4*>(&g_perc[(k0 + bk + 8) * NPIX + bn + bnq]);
    };
    auto stAB = [&]() {
        #pragma unroll
        for (int it = 0; it < 2; it++) {
            const int m = am + it * 64;
            const float vv[4] = {pa[it].x, pa[it].y, pa[it].z, pa[it].w};
            #pragma unroll
            for (int j = 0; j < 4; j++) {
                float hi = tf32r(vv[j]);
                sAh[(akq + j) * RS + m] = hi;
                sAl[(akq + j) * RS + m] = tf32r(vv[j] - hi);
            }
        }
        #pragma unroll
        for (int it = 0; it < 2; it++) {
            const int k = bk + it * 8;
            float4 v = pb[it];
            float4 h, l;
            h.x = tf32r(v.x); l.x = tf32r(v.x - h.x);
            h.y = tf32r(v.y); l.y = tf32r(v.y - h.y);
            h.z = tf32r(v.z); l.z = tf32r(v.z - h.z);
            h.w = tf32r(v.w); l.w = tf32r(v.w - h.w);
            *reinterpret_cast<float4*>(&sBh[k * RS + bnq]) = h;
            *reinterpret_cast<float4*>(&sBl[k * RS + bnq]) = l;
        }
    };

    ldA(0); ldB(0);
    stAB();
    __syncthreads();

    const int NCH = HID / 16;   // 32
    #pragma unroll 1
    for (int c = 0; c < NCH; c++) {
        const bool more = (c + 1 < NCH);
        if (more) { ldA((c + 1) * 16); ldB((c + 1) * 16); }

        #pragma unroll
        for (int k8 = 0; k8 < 16; k8 += 8) {
            const int krow = (k8 + lc) * RS;
            uint32_t ah[2][4], al[2][4];
            #pragma unroll
            for (int mi = 0; mi < 2; mi++) {
                const int mb = wm * 32 + mi * 16 + lr;
                ah[mi][0] = __float_as_uint(sAh[krow + mb]);
                ah[mi][1] = __float_as_uint(sAh[krow + mb + 8]);
                ah[mi][2] = __float_as_uint(sAh[krow + 4 * RS + mb]);
                ah[mi][3] = __float_as_uint(sAh[krow + 4 * RS + mb + 8]);
                al[mi][0] = __float_as_uint(sAl[krow + mb]);
                al[mi][1] = __float_as_uint(sAl[krow + mb + 8]);
                al[mi][2] = __float_as_uint(sAl[krow + 4 * RS + mb]);
                al[mi][3] = __float_as_uint(sAl[krow + 4 * RS + mb + 8]);
            }
            #pragma unroll
            for (int ni = 0; ni < 8; ni++) {
                const int nbase = wn * 64 + ni * 8 + lr;
                const uint32_t bh0 = __float_as_uint(sBh[krow + nbase]);
                const uint32_t bh1 = __float_as_uint(sBh[krow + 4 * RS + nbase]);
                const uint32_t bl0 = __float_as_uint(sBl[krow + nbase]);
                const uint32_t bl1 = __float_as_uint(sBl[krow + 4 * RS + nbase]);
                #pragma unroll
                for (int mi = 0; mi < 2; mi++) {
                    MMA_TF32(acc[mi][ni], ah[mi][0], ah[mi][1], ah[mi][2], ah[mi][3], bh0, bh1);
                    MMA_TF32(acc[mi][ni], ah[mi][0], ah[mi][1], ah[mi][2], ah[mi][3], bl0, bl1);
                    MMA_TF32(acc[mi][ni], al[mi][0], al[mi][1], al[mi][2], al[mi][3], bh0, bh1);
                }
            }
        }

        __syncthreads();
        if (more) { stAB(); __syncthreads(); }
    }

    float bv[2][2];
    #pragma unroll
    for (int mi = 0; mi < 2; mi++)
        #pragma unroll
        for (int hh = 0; hh < 2; hh++)
            bv[mi][hh] = b2[bm + wm * 32 + mi * 16 + lr + hh * 8];

    #pragma unroll
    for (int mi = 0; mi < 2; mi++)
        #pragma unroll
        for (int ni = 0; ni < 8; ni++)
            #pragma unroll
            for (int cr = 0; cr < 4; cr++) {
                const int m   = bm + wm * 32 + mi * 16 + lr + (cr >> 1) * 8;
                const int pix = bn + wn * 64 + ni * 8 + lc * 2 + (cr & 1);
                g_h[m * NPIX + pix] = fmaxf(acc[mi][ni][cr] + bv[mi][cr >> 1], 0.f);
            }
}

// ---------------------------------------------------------------------------
// GEMM3: tmp = W3 @ h + b3 + state   (80 x 8192 x 512) — scalar (small)
// ---------------------------------------------------------------------------
#define BK 16
#define BM3 80
#define BN3 64

__global__ __launch_bounds__(256) void k_gemm_upd(const float* __restrict__ W3,
                                                  const float* __restrict__ b3,
                                                  int s) {
    const int bn = blockIdx.x * BN3;
    const int y0 = (bn & 1023) >> 5;
    if (y0 + 1 < 14 - s || y0 > 18 + s) return;

    __shared__ float As[BK][BM3];
    __shared__ float Bs[BK][BN3];
    const int tid = threadIdx.x;
    const int tx = tid & 15, ty = tid >> 4;

    float acc[5][4];
    #pragma unroll
    for (int i = 0; i < 5; i++)
        #pragma unroll
        for (int j = 0; j < 4; j++) acc[i][j] = 0.f;

    for (int k0 = 0; k0 < HID; k0 += BK) {
        #pragma unroll
        for (int it = 0; it < 5; it++) {
            int f = tid + it * 256;
            int m = f >> 4, k = f & 15;
            As[k][m] = W3[m * HID + k0 + k];
        }
        {
            int k  = tid >> 4;
            int nq = (tid & 15) * 4;
            float4 v = *reinterpret_cast<const float4*>(&g_h[(k0 + k) * NPIX + bn + nq]);
            *reinterpret_cast<float4*>(&Bs[k][nq]) = v;
        }
        __syncthreads();
        #pragma unroll
        for (int k = 0; k < BK; k++) {
            float a[5], b[4];
            #pragma unroll
            for (int i = 0; i < 5; i++) a[i] = As[k][ty + 16 * i];
            #pragma unroll
            for (int j = 0; j < 4; j++) b[j] = Bs[k][tx + 16 * j];
            #pragma unroll
            for (int i = 0; i < 5; i++)
                #pragma unroll
                for (int j = 0; j < 4; j++)
                    acc[i][j] = fmaf(a[i], b[j], acc[i][j]);
        }
        __syncthreads();
    }
    #pragma unroll
    for (int i = 0; i < 5; i++) {
        int m = ty + 16 * i;
        float bias = b3[m];
        #pragma unroll
        for (int j = 0; j < 4; j++) {
            int idx = m * NPIX + bn + tx + 16 * j;
            g_tmp[idx] = acc[i][j] + bias + g_state[idx];
        }
    }
}

// ---------------------------------------------------------------------------
// finalize (fused)
// ---------------------------------------------------------------------------
__device__ __forceinline__ float maxpool_s(const float* s0, int pp) {
    int x = pp & 31, y = pp >> 5;
    float m = -1e30f;
    #pragma unroll
    for (int dy = -1; dy <= 1; dy++) {
        int yy = y + dy;
        if ((unsigned)yy >= 32u) continue;
        #pragma unroll
        for (int dx = -1; dx <= 1; dx++) {
            int xx = x + dx;
            if ((unsigned)xx >= 32u) continue;
            m = fmaxf(m, s0[pp + dy * 32 + dx]);
        }
    }
    return m;
}

__global__ __launch_bounds__(256) void k_finalize() {
    __shared__ float s0[1024];
    __shared__ unsigned char alv[1024];
    const int base = blockIdx.x * 1024;
    const int t = threadIdx.x;

    #pragma unroll
    for (int r = 0; r < 4; r++) {
        int pp = t + r * 256;
        s0[pp] = g_tmp[base + pp];
    }
    __syncthreads();

    #pragma unroll
    for (int r = 0; r < 4; r++) {
        int pp = t + r * 256;
        float post = maxpool_s(s0, pp);
        alv[pp] = (post > CA_THRESH) && g_pre[base + pp];
    }
    __syncthreads();

    #pragma unroll
    for (int r = 0; r < 4; r++) {
        int pp = t + r * 256;
        bool a = alv[pp];
        #pragma unroll 4
        for (int c = 0; c < SS; c++) {
            int idx = c * NPIX + base + pp;
            g_state[idx] = a ? g_tmp[idx] : 0.f;
        }
        s0[pp] = a ? s0[pp] : 0.f;
    }
    __syncthreads();

    #pragma unroll
    for (int r = 0; r < 4; r++) {
        int pp = t + r * 256;
        g_pre[base + pp] = (maxpool_s(s0, pp) > CA_THRESH) ? 1 : 0;
    }
}

__global__ void k_out(float* __restrict__ out) {
    int p = blockIdx.x * blockDim.x + threadIdx.x;
    if (p < NPIX) out[p] = g_state[p];
}

// ---------------------------------------------------------------------------
// launch
// ---------------------------------------------------------------------------
extern "C" void kernel_launch(void* const* d_in, const int* in_sizes, int n_in,
                              void* d_out, int out_size) {
    const float* z  = (const float*)d_in[0];
    const float* W1 = (const float*)d_in[1];
    const float* b1 = (const float*)d_in[2];
    const float* W2 = (const float*)d_in[3];
    const float* b2 = (const float*)d_in[4];
    const float* W3 = (const float*)d_in[5];
    const float* b3 = (const float*)d_in[6];

    k_zero_state<<<(SS * NPIX + 255) / 256, 256>>>();
    k_init<<<3, 256>>>(z);
    k_pre<<<NPIX / 256, 256>>>();   // pre-living for step 0

    dim3 g12(NPIX / 128, HID / 128);   // (64, 4)
    for (int s = 0; s < 64; s++) {
        k_gemm_conv<<<g12, 256>>>(W1, b1, s);
        k_gemm_h<<<g12, 256>>>(W2, b2, s);
        k_gemm_upd<<<NPIX / BN3, 256>>>(W3, b3, s);
        k_finalize<<<8, 256>>>();
    }
    k_out<<<NPIX / 256, 256>>>((float*)d_out);
}

// round 16
// speedup vs baseline: 1.1969x; 1.1969x over previous
#include <cuda_runtime.h>
#include <cstdint>

#define SS    80
#define HID   512
#define NPIX  8192      // 8 images * 32*32
#define KCONV 720       // 80 * 9
#define CA_THRESH 0.01f

// Internal buffers (allocation-free: __device__ globals)
__device__ float g_state[SS * NPIX];
__device__ float g_tmp[SS * NPIX];
__device__ float g_perc[HID * NPIX];
__device__ float g_h[HID * NPIX];
__device__ unsigned char g_pre[NPIX];
// pre-split + pre-transposed weights: [k][m] layout, tf32 hi/lo
__device__ float g_W1h[KCONV * HID], g_W1l[KCONV * HID];
__device__ float g_W2h[HID * HID],   g_W2l[HID * HID];

// ---------------------------------------------------------------------------
// helpers
// ---------------------------------------------------------------------------
__device__ __forceinline__ float tf32r(float x) {
    uint32_t u; asm("cvt.rna.tf32.f32 %0, %1;" : "=r"(u) : "f"(x));
    return __uint_as_float(u);
}

#define MMA_TF32(c, a0_, a1_, a2_, a3_, b0_, b1_) \
    asm volatile("mma.sync.aligned.m16n8k8.row.col.f32.tf32.tf32.f32 " \
        "{%0,%1,%2,%3}, {%4,%5,%6,%7}, {%8,%9}, {%0,%1,%2,%3};" \
        : "+f"((c)[0]), "+f"((c)[1]), "+f"((c)[2]), "+f"((c)[3]) \
        : "r"(a0_), "r"(a1_), "r"(a2_), "r"(a3_), "r"(b0_), "r"(b1_))

// smem row stride for [k][x] tiles: 136 floats (136 mod 32 = 8 -> fragment
// reads at banks 8*lc+lr, all 32 distinct; conflict-free).
#define RS 136

// ---------------------------------------------------------------------------
// weight prep (once per launch): transpose to [k][m], tf32 hi/lo split
// ---------------------------------------------------------------------------
__global__ void k_prep_w1(const float* __restrict__ W1) {
    int t = blockIdx.x * blockDim.x + threadIdx.x;
    if (t >= KCONV * HID) return;
    int k = t >> 9, m = t & 511;
    float v = W1[m * KCONV + k];
    float hi = tf32r(v);
    g_W1h[t] = hi;
    g_W1l[t] = tf32r(v - hi);
}
__global__ void k_prep_w2(const float* __restrict__ W2) {
    int t = blockIdx.x * blockDim.x + threadIdx.x;
    if (t >= HID * HID) return;
    int k = t >> 9, m = t & 511;
    float v = W2[m * HID + k];
    float hi = tf32r(v);
    g_W2h[t] = hi;
    g_W2l[t] = tf32r(v - hi);
}

// ---------------------------------------------------------------------------
// init
// ---------------------------------------------------------------------------
__global__ void k_zero_state() {
    int i = blockIdx.x * blockDim.x + threadIdx.x;
    if (i < SS * NPIX) g_state[i] = 0.f;
}

__global__ void k_init(const float* __restrict__ z) {
    int t = blockIdx.x * blockDim.x + threadIdx.x;
    if (t >= 8 * SS) return;
    int n = t / SS, c = t % SS;
    int p = n * 1024 + 16 * 32 + 16;
    float v = (c == 0) ? 1.0f : z[n * 100 + (c - 1)];
    g_state[c * NPIX + p] = v;
}

__device__ __forceinline__ float maxpool3(const float* __restrict__ row, int p) {
    int x = p & 31, y = (p >> 5) & 31;
    float m = -1e30f;
    #pragma unroll
    for (int dy = -1; dy <= 1; dy++) {
        int yy = y + dy;
        if ((unsigned)yy >= 32u) continue;
        #pragma unroll
        for (int dx = -1; dx <= 1; dx++) {
            int xx = x + dx;
            if ((unsigned)xx >= 32u) continue;
            m = fmaxf(m, row[p + dy * 32 + dx]);
        }
    }
    return m;
}

__global__ void k_pre() {
    int p = blockIdx.x * blockDim.x + threadIdx.x;
    if (p >= NPIX) return;
    g_pre[p] = (maxpool3(g_state, p) > CA_THRESH) ? 1 : 0;
}

// ---------------------------------------------------------------------------
// mma compute core (shared by both GEMMs): one 16-deep k-chunk from smem
// ---------------------------------------------------------------------------
#define MMA_CHUNK()                                                            \
    _Pragma("unroll")                                                          \
    for (int k8 = 0; k8 < 16; k8 += 8) {                                       \
        const int krow = (k8 + lc) * RS;                                       \
        uint32_t ah[2][4], al[2][4];                                           \
        _Pragma("unroll")                                                      \
        for (int mi = 0; mi < 2; mi++) {                                       \
            const int mb = wm * 32 + mi * 16 + lr;                             \
            ah[mi][0] = __float_as_uint(sAh[krow + mb]);                       \
            ah[mi][1] = __float_as_uint(sAh[krow + mb + 8]);                   \
            ah[mi][2] = __float_as_uint(sAh[krow + 4 * RS + mb]);              \
            ah[mi][3] = __float_as_uint(sAh[krow + 4 * RS + mb + 8]);          \
            al[mi][0] = __float_as_uint(sAl[krow + mb]);                       \
            al[mi][1] = __float_as_uint(sAl[krow + mb + 8]);                   \
            al[mi][2] = __float_as_uint(sAl[krow + 4 * RS + mb]);              \
            al[mi][3] = __float_as_uint(sAl[krow + 4 * RS + mb + 8]);          \
        }                                                                      \
        _Pragma("unroll")                                                      \
        for (int ni = 0; ni < 8; ni++) {                                       \
            const int nbase = wn * 64 + ni * 8 + lr;                           \
            const uint32_t bh0 = __float_as_uint(sBh[krow + nbase]);           \
            const uint32_t bh1 = __float_as_uint(sBh[krow + 4 * RS + nbase]);  \
            const uint32_t bl0 = __float_as_uint(sBl[krow + nbase]);           \
            const uint32_t bl1 = __float_as_uint(sBl[krow + 4 * RS + nbase]);  \
            _Pragma("unroll")                                                  \
            for (int mi = 0; mi < 2; mi++) {                                   \
                MMA_TF32(acc[mi][ni], ah[mi][0], ah[mi][1], ah[mi][2], ah[mi][3], bh0, bh1); \
                MMA_TF32(acc[mi][ni], ah[mi][0], ah[mi][1], ah[mi][2], ah[mi][3], bl0, bl1); \
                MMA_TF32(acc[mi][ni], al[mi][0], al[mi][1], al[mi][2], al[mi][3], bh0, bh1); \
            }                                                                  \
        }                                                                      \
    }

// ---------------------------------------------------------------------------
// GEMM1 (mma tf32x3): perception = W1 (*) im2col(state) + b1  (512x8192x720)
// CTA 128m x 128n, 256 thr, occupancy 2 (single wave at grid 256).
// A staged from pre-split/transposed g_W1h/l via float4 copies.
// ---------------------------------------------------------------------------
__global__ __launch_bounds__(256, 2) void k_gemm_conv(const float* __restrict__ b1,
                                                      int s) {
    const int bm = blockIdx.y * 128;
    const int bn = blockIdx.x * 128;

    // active-box early exit (output rows [14-s, 18+s]); block-uniform
    const int y0 = (bn & 1023) >> 5;
    if (y0 + 3 < 14 - s || y0 > 18 + s) return;

    __shared__ float sAh[16 * RS], sAl[16 * RS];
    __shared__ float sBh[16 * RS], sBl[16 * RS];

    const int tid  = threadIdx.x;
    const int wid  = tid >> 5, lane = tid & 31;
    const int wm   = wid & 3,  wn   = wid >> 2;
    const int lr   = lane >> 2, lc  = lane & 3;

    // A-stage identity: f = tid + it*256 -> kk = f>>5 (0..15), mq = (f&31)*4
    const int ak  = tid >> 5;
    const int amq = (tid & 31) * 4;
    // B-gather identity
    const int nb = tid & 127;
    const int p  = bn + nb;
    const int x  = p & 31, y = (p >> 5) & 31;
    const int kb = tid >> 7;   // 0 or 1

    float acc[2][8][4];
    #pragma unroll
    for (int mi = 0; mi < 2; mi++)
        #pragma unroll
        for (int ni = 0; ni < 8; ni++)
            #pragma unroll
            for (int cr = 0; cr < 4; cr++) acc[mi][ni][cr] = 0.f;

    const int NCH = KCONV / 16;   // 45
    #pragma unroll 1
    for (int c = 0; c < NCH; c++) {
        const int k0 = c * 16;
        if (c > 0) __syncthreads();   // protect previous chunk's smem reads

        // stage A: float4 copies from pre-split transposed weights
        #pragma unroll
        for (int it = 0; it < 2; it++) {
            const int kk = ak + it * 8;
            const size_t go = (size_t)(k0 + kk) * HID + bm + amq;
            *reinterpret_cast<float4*>(&sAh[kk * RS + amq]) =
                *reinterpret_cast<const float4*>(&g_W1h[go]);
            *reinterpret_cast<float4*>(&sAl[kk * RS + amq]) =
                *reinterpret_cast<const float4*>(&g_W1l[go]);
        }
        // stage B: boundary-masked gather from state + tf32 split
        #pragma unroll
        for (int it = 0; it < 8; it++) {
            int k  = k0 + kb + it * 2;
            int ci = k / 9;
            int r  = k - ci * 9;
            int dy = r / 3 - 1;
            int dx = r - (dy + 1) * 3 - 1;
            int yy = y + dy, xx = x + dx;
            float v = 0.f;
            if ((unsigned)yy < 32u && (unsigned)xx < 32u)
                v = g_state[ci * NPIX + p + dy * 32 + dx];
            float hi = tf32r(v);
            sBh[(kb + it * 2) * RS + nb] = hi;
            sBl[(kb + it * 2) * RS + nb] = tf32r(v - hi);
        }
        __syncthreads();

        MMA_CHUNK()
    }

    // epilogue: +bias, float2 stores (adjacent pixels per acc pair)
    float bv[2][2];
    #pragma unroll
    for (int mi = 0; mi < 2; mi++)
        #pragma unroll
        for (int hh = 0; hh < 2; hh++)
            bv[mi][hh] = b1[bm + wm * 32 + mi * 16 + lr + hh * 8];

    #pragma unroll
    for (int mi = 0; mi < 2; mi++)
        #pragma unroll
        for (int ni = 0; ni < 8; ni++) {
            const int pix = bn + wn * 64 + ni * 8 + lc * 2;
            #pragma unroll
            for (int hh = 0; hh < 2; hh++) {
                const int m = bm + wm * 32 + mi * 16 + lr + hh * 8;
                float2 v = make_float2(acc[mi][ni][2 * hh]     + bv[mi][hh],
                                       acc[mi][ni][2 * hh + 1] + bv[mi][hh]);
                *reinterpret_cast<float2*>(&g_perc[m * NPIX + pix]) = v;
            }
        }
}

// ---------------------------------------------------------------------------
// GEMM2 (mma tf32x3): h = relu(W2 @ perception + b2)   (512 x 8192 x 512)
// ---------------------------------------------------------------------------
__global__ __launch_bounds__(256, 2) void k_gemm_h(const float* __restrict__ b2,
                                                   int s) {
    const int bm = blockIdx.y * 128;
    const int bn = blockIdx.x * 128;

    const int y0 = (bn & 1023) >> 5;
    if (y0 + 3 < 14 - s || y0 > 18 + s) return;

    __shared__ float sAh[16 * RS], sAl[16 * RS];
    __shared__ float sBh[16 * RS], sBl[16 * RS];

    const int tid  = threadIdx.x;
    const int wid  = tid >> 5, lane = tid & 31;
    const int wm   = wid & 3,  wn   = wid >> 2;
    const int lr   = lane >> 2, lc  = lane & 3;

    const int ak  = tid >> 5;
    const int amq = (tid & 31) * 4;
    // B-stage identity: same pattern (16 k-rows x 128 pixels, float4)
    const int bkk = tid >> 5;
    const int bnq = (tid & 31) * 4;

    float acc[2][8][4];
    #pragma unroll
    for (int mi = 0; mi < 2; mi++)
        #pragma unroll
        for (int ni = 0; ni < 8; ni++)
            #pragma unroll
            for (int cr = 0; cr < 4; cr++) acc[mi][ni][cr] = 0.f;

    const int NCH = HID / 16;   // 32
    #pragma unroll 1
    for (int c = 0; c < NCH; c++) {
        const int k0 = c * 16;
        if (c > 0) __syncthreads();

        #pragma unroll
        for (int it = 0; it < 2; it++) {
            const int kk = ak + it * 8;
            const size_t go = (size_t)(k0 + kk) * HID + bm + amq;
            *reinterpret_cast<float4*>(&sAh[kk * RS + amq]) =
                *reinterpret_cast<const float4*>(&g_W2h[go]);
            *reinterpret_cast<float4*>(&sAl[kk * RS + amq]) =
                *reinterpret_cast<const float4*>(&g_W2l[go]);
        }
        #pragma unroll
        for (int it = 0; it < 2; it++) {
            const int kk = bkk + it * 8;
            float4 v = *reinterpret_cast<const float4*>(
                &g_perc[(size_t)(k0 + kk) * NPIX + bn + bnq]);
            float4 h, l;
            h.x = tf32r(v.x); l.x = tf32r(v.x - h.x);
            h.y = tf32r(v.y); l.y = tf32r(v.y - h.y);
            h.z = tf32r(v.z); l.z = tf32r(v.z - h.z);
            h.w = tf32r(v.w); l.w = tf32r(v.w - h.w);
            *reinterpret_cast<float4*>(&sBh[kk * RS + bnq]) = h;
            *reinterpret_cast<float4*>(&sBl[kk * RS + bnq]) = l;
        }
        __syncthreads();

        MMA_CHUNK()
    }

    float bv[2][2];
    #pragma unroll
    for (int mi = 0; mi < 2; mi++)
        #pragma unroll
        for (int hh = 0; hh < 2; hh++)
            bv[mi][hh] = b2[bm + wm * 32 + mi * 16 + lr + hh * 8];

    #pragma unroll
    for (int mi = 0; mi < 2; mi++)
        #pragma unroll
        for (int ni = 0; ni < 8; ni++) {
            const int pix = bn + wn * 64 + ni * 8 + lc * 2;
            #pragma unroll
            for (int hh = 0; hh < 2; hh++) {
                const int m = bm + wm * 32 + mi * 16 + lr + hh * 8;
                float2 v = make_float2(
                    fmaxf(acc[mi][ni][2 * hh]     + bv[mi][hh], 0.f),
                    fmaxf(acc[mi][ni][2 * hh + 1] + bv[mi][hh], 0.f));
                *reinterpret_cast<float2*>(&g_h[m * NPIX + pix]) = v;
            }
        }
}

// ---------------------------------------------------------------------------
// GEMM3: tmp = W3 @ h + b3 + state   (80 x 8192 x 512) — scalar (small)
// ---------------------------------------------------------------------------
#define BK 16
#define BM3 80
#define BN3 64

__global__ __launch_bounds__(256) void k_gemm_upd(const float* __restrict__ W3,
                                                  const float* __restrict__ b3,
                                                  int s) {
    const int bn = blockIdx.x * BN3;
    const int y0 = (bn & 1023) >> 5;
    if (y0 + 1 < 14 - s || y0 > 18 + s) return;

    __shared__ float As[BK][BM3];
    __shared__ float Bs[BK][BN3];
    const int tid = threadIdx.x;
    const int tx = tid & 15, ty = tid >> 4;

    float acc[5][4];
    #pragma unroll
    for (int i = 0; i < 5; i++)
        #pragma unroll
        for (int j = 0; j < 4; j++) acc[i][j] = 0.f;

    for (int k0 = 0; k0 < HID; k0 += BK) {
        #pragma unroll
        for (int it = 0; it < 5; it++) {
            int f = tid + it * 256;
            int m = f >> 4, k = f & 15;
            As[k][m] = W3[m * HID + k0 + k];
        }
        {
            int k  = tid >> 4;
            int nq = (tid & 15) * 4;
            float4 v = *reinterpret_cast<const float4*>(&g_h[(k0 + k) * NPIX + bn + nq]);
            *reinterpret_cast<float4*>(&Bs[k][nq]) = v;
        }
        __syncthreads();
        #pragma unroll
        for (int k = 0; k < BK; k++) {
            float a[5], b[4];
            #pragma unroll
            for (int i = 0; i < 5; i++) a[i] = As[k][ty + 16 * i];
            #pragma unroll
            for (int j = 0; j < 4; j++) b[j] = Bs[k][tx + 16 * j];
            #pragma unroll
            for (int i = 0; i < 5; i++)
                #pragma unroll
                for (int j = 0; j < 4; j++)
                    acc[i][j] = fmaf(a[i], b[j], acc[i][j]);
        }
        __syncthreads();
    }
    #pragma unroll
    for (int i = 0; i < 5; i++) {
        int m = ty + 16 * i;
        float bias = b3[m];
        #pragma unroll
        for (int j = 0; j < 4; j++) {
            int idx = m * NPIX + bn + tx + 16 * j;
            g_tmp[idx] = acc[i][j] + bias + g_state[idx];
        }
    }
}

// ---------------------------------------------------------------------------
// finalize (fused)
// ---------------------------------------------------------------------------
__device__ __forceinline__ float maxpool_s(const float* s0, int pp) {
    int x = pp & 31, y = pp >> 5;
    float m = -1e30f;
    #pragma unroll
    for (int dy = -1; dy <= 1; dy++) {
        int yy = y + dy;
        if ((unsigned)yy >= 32u) continue;
        #pragma unroll
        for (int dx = -1; dx <= 1; dx++) {
            int xx = x + dx;
            if ((unsigned)xx >= 32u) continue;
            m = fmaxf(m, s0[pp + dy * 32 + dx]);
        }
    }
    return m;
}

__global__ __launch_bounds__(256) void k_finalize() {
    __shared__ float s0[1024];
    __shared__ unsigned char alv[1024];
    const int base = blockIdx.x * 1024;
    const int t = threadIdx.x;

    #pragma unroll
    for (int r = 0; r < 4; r++) {
        int pp = t + r * 256;
        s0[pp] = g_tmp[base + pp];
    }
    __syncthreads();

    #pragma unroll
    for (int r = 0; r < 4; r++) {
        int pp = t + r * 256;
        float post = maxpool_s(s0, pp);
        alv[pp] = (post > CA_THRESH) && g_pre[base + pp];
    }
    __syncthreads();

    #pragma unroll
    for (int r = 0; r < 4; r++) {
        int pp = t + r * 256;
        bool a = alv[pp];
        #pragma unroll 4
        for (int c = 0; c < SS; c++) {
            int idx = c * NPIX + base + pp;
            g_state[idx] = a ? g_tmp[idx] : 0.f;
        }
        s0[pp] = a ? s0[pp] : 0.f;
    }
    __syncthreads();

    #pragma unroll
    for (int r = 0; r < 4; r++) {
        int pp = t + r * 256;
        g_pre[base + pp] = (maxpool_s(s0, pp) > CA_THRESH) ? 1 : 0;
    }
}

__global__ void k_out(float* __restrict__ out) {
    int p = blockIdx.x * blockDim.x + threadIdx.x;
    if (p < NPIX) out[p] = g_state[p];
}

// ---------------------------------------------------------------------------
// launch
// ---------------------------------------------------------------------------
extern "C" void kernel_launch(void* const* d_in, const int* in_sizes, int n_in,
                              void* d_out, int out_size) {
    const float* z  = (const float*)d_in[0];
    const float* W1 = (const float*)d_in[1];
    const float* b1 = (const float*)d_in[2];
    const float* W2 = (const float*)d_in[3];
    const float* b2 = (const float*)d_in[4];
    const float* W3 = (const float*)d_in[5];
    const float* b3 = (const float*)d_in[6];

    k_prep_w1<<<(KCONV * HID + 255) / 256, 256>>>(W1);
    k_prep_w2<<<(HID * HID + 255) / 256, 256>>>(W2);
    k_zero_state<<<(SS * NPIX + 255) / 256, 256>>>();
    k_init<<<3, 256>>>(z);
    k_pre<<<NPIX / 256, 256>>>();   // pre-living for step 0

    dim3 g12(NPIX / 128, HID / 128);   // (64, 4)
    for (int s = 0; s < 64; s++) {
        k_gemm_conv<<<g12, 256>>>(b1, s);
        k_gemm_h<<<g12, 256>>>(b2, s);
        k_gemm_upd<<<NPIX / BN3, 256>>>(W3, b3, s);
        k_finalize<<<8, 256>>>();
    }
    k_out<<<NPIX / 256, 256>>>((float*)d_out);
}